// round 8
// baseline (speedup 1.0000x reference)
#include <cuda_runtime.h>
#include <cuda_bf16.h>
#include <cstdint>
#include <math.h>

#define Bsz 32
#define Tsz 512
#define DIsz 512
#define Hsz 512
#define G4 2048
#define G5 2560
#define NCTA 148
#define NTHR 512
#define BTHn ((size_t)32*512*512)

typedef unsigned int uint;
typedef unsigned short ushort;

// ---- static device scratch ----
// h stored as bf16 hi/lo in MMA B-FRAGMENT layout:
//   block per (layer,t): 8192 uints; uintIdx = (j>>4)*256 + ((j&15)>>1)*32 + (b&7)*4 + (b>>3)
//   ushort sub-index = j&1
static __device__ __align__(16) uint g_fhi[(size_t)4*512*8192];
static __device__ __align__(16) uint g_flo[(size_t)4*512*8192];
static __device__ float g_c[(size_t)4*512*32*512];
static __device__ float g_xt[(size_t)512*2048*32];           // [t][rowp][b]
static __device__ __align__(16) uint g_wA0[(size_t)16*16*32*128];    // L0 frags
static __device__ __align__(16) uint g_wAca[(size_t)132*16*32*128];  // CA frags
static __device__ unsigned g_done[4];                        // per-layer step counters

#define PSTR 4224            // 128*33 floats per kw partial region

__device__ __forceinline__ float sigf(float x) { return 1.0f / (1.0f + __expf(-x)); }

__device__ __forceinline__ ushort bfhi(float w) {
    return __bfloat16_as_ushort(__float2bfloat16(w));
}
__device__ __forceinline__ ushort bflo(float w) {
    float h = __bfloat162float(__float2bfloat16(w));
    return __bfloat16_as_ushort(__float2bfloat16(w - h));
}

__device__ __forceinline__ void mma_bf16(float* d, const uint4& a, uint b0, uint b1) {
    asm volatile(
        "mma.sync.aligned.m16n8k16.row.col.f32.bf16.bf16.f32 "
        "{%0,%1,%2,%3},{%4,%5,%6,%7},{%8,%9},{%0,%1,%2,%3};"
        : "+f"(d[0]), "+f"(d[1]), "+f"(d[2]), "+f"(d[3])
        : "r"(a.x), "r"(a.y), "r"(a.z), "r"(a.w), "r"(b0), "r"(b1));
}

static __device__ __host__ __forceinline__ void cta_params(int ci, int& nj, int& j0) {
    if (ci < 28) { nj = 12; j0 = ci * 12; }
    else         { nj = 11; j0 = 336 + (ci - 28) * 11; }
}

// fragment uint index for h pair (j&~1, j|1), batch b
__device__ __forceinline__ int frag_idx(int j, int b) {
    return (j >> 4) * 256 + ((j & 15) >> 1) * 32 + (b & 7) * 4 + (b >> 3);
}

// ---------------- weight fragment packing + counter reset ----------------
__global__ void __launch_bounds__(256) k_fill(const float* __restrict__ w_hh,
                                              const float* __restrict__ ca_w)
{
    size_t stride = (size_t)gridDim.x * blockDim.x;
    size_t i0 = (size_t)blockIdx.x * blockDim.x + threadIdx.x;
    if (i0 < 4) g_done[i0] = 0u;

    const size_t N0 = (size_t)16*16*32*128;
    for (size_t e = i0; e < N0; e += stride) {
        int reg = (int)(e & 3), lane = (int)((e >> 2) & 31), f = (int)((e >> 7) & 31);
        int wid = (int)((e >> 12) & 15), cta = (int)(e >> 16);
        int part = f & 1, mt = (f >> 1) & 1, ks = f >> 2;
        int mw = wid >> 2, kw = wid & 3;
        int gr = lane >> 2, c0 = (lane & 3) * 2;
        int slot = mw * 32 + mt * 16 + gr + (reg & 1) * 8;
        int kk = kw * 128 + ks * 16 + c0 + ((reg >> 1) & 1) * 8;
        int row = (slot >> 5) * 512 + cta * 32 + (slot & 31);
        float w0 = w_hh[(size_t)row * 512 + kk];
        float w1 = w_hh[(size_t)row * 512 + kk + 1];
        ushort u0 = part ? bflo(w0) : bfhi(w0);
        ushort u1 = part ? bflo(w1) : bfhi(w1);
        g_wA0[e] = (uint)u0 | ((uint)u1 << 16);
    }
    const size_t NC = (size_t)132*16*32*128;
    for (size_t e = i0; e < NC; e += stride) {
        int reg = (int)(e & 3), lane = (int)((e >> 2) & 31), f = (int)((e >> 7) & 31);
        int wid = (int)((e >> 12) & 15), lc = (int)(e >> 16);
        int part = f & 1, ks = f >> 1;
        int mw = wid >> 2, kw = wid & 3;
        int gr = lane >> 2, c0 = (lane & 3) * 2;
        int slot = mw * 16 + gr + (reg & 1) * 8;
        int kk = kw * 256 + ks * 16 + c0 + ((reg >> 1) & 1) * 8;
        int ci = lc % 44, l = lc / 44;
        int nj, j0; cta_params(ci, nj, j0);
        float w0 = 0.0f, w1 = 0.0f;
        if (slot < 5 * nj) {
            int g = slot / nj, jj = slot - g * nj;
            int row = g * 512 + j0 + jj;
            w0 = ca_w[((size_t)l * G5 + row) * 1024 + kk];
            w1 = ca_w[((size_t)l * G5 + row) * 1024 + kk + 1];
        }
        ushort u0 = part ? bflo(w0) : bfhi(w0);
        ushort u1 = part ? bflo(w1) : bfhi(w1);
        g_wAca[e] = (uint)u0 | ((uint)u1 << 16);
    }
}

// ---------------- xproj = x @ w_ih.T + bias, stored [t][rowp][b] ----------------
__global__ void __launch_bounds__(256) k_xproj(
    const float* __restrict__ x, const float* __restrict__ w_ih,
    const float* __restrict__ b_ih, const float* __restrict__ b_hh)
{
    __shared__ float As[16][65];
    __shared__ float Bs[16][65];
    const int bm = blockIdx.y * 64, bn = blockIdx.x * 64;
    const int tid = threadIdx.x;
    const int tr = (tid >> 4) << 2, tc = (tid & 15) << 2;
    float acc[4][4] = {};
    for (int k0 = 0; k0 < DIsz; k0 += 16) {
        #pragma unroll
        for (int i0 = 0; i0 < 4; i0++) {
            int i = i0 * 256 + tid;
            int mm = i >> 4, kk = i & 15;
            int m = bm + mm, tt = m >> 5, bb = m & 31;
            As[kk][mm] = x[((size_t)bb * Tsz + tt) * DIsz + (k0 + kk)];
            Bs[kk][mm] = w_ih[(size_t)(bn + mm) * DIsz + (k0 + kk)];
        }
        __syncthreads();
        #pragma unroll
        for (int kk = 0; kk < 16; kk++) {
            float a[4] = {As[kk][tr], As[kk][tr+1], As[kk][tr+2], As[kk][tr+3]};
            float b[4] = {Bs[kk][tc], Bs[kk][tc+1], Bs[kk][tc+2], Bs[kk][tc+3]};
            #pragma unroll
            for (int i = 0; i < 4; i++)
                #pragma unroll
                for (int j = 0; j < 4; j++)
                    acc[i][j] = fmaf(a[i], b[j], acc[i][j]);
        }
        __syncthreads();
    }
    #pragma unroll
    for (int i = 0; i < 4; i++) {
        int m = bm + tr + i, tt = m >> 5, bb = m & 31;
        #pragma unroll
        for (int j = 0; j < 4; j++) {
            int n = bn + tc + j;
            int g = n >> 9, cd = (n >> 5) & 15, jj = n & 31;
            g_xt[((size_t)tt * 2048 + cd * 128 + g * 32 + jj) * 32 + bb]
                = acc[i][j] + b_ih[n] + b_hh[n];
        }
    }
}

// ---------------- persistent self-timed LSTM, fragment-direct GEMM ----------------
__global__ void __launch_bounds__(NTHR, 1) k_wave(
    const float* __restrict__ ca_b, float* __restrict__ out)
{
    extern __shared__ char smx[];
    float* part = (float*)smx;

    const int tid  = threadIdx.x;
    const int lane = tid & 31;
    const int wid  = tid >> 5;
    const int cta  = blockIdx.x;
    const int mw = wid >> 2, kw = wid & 3;
    const int gr = lane >> 2, c0 = (lane & 3) * 2;
    const int lanepart = (lane & 3) * 32 + (lane >> 2) * 4;  // uint offset within ktile

    int layer, j0, nj, ci = 0;
    if (cta < 16) { layer = 0; nj = 32; j0 = cta * 32; }
    else {
        int r = cta - 16;
        layer = 1 + r / 44;
        ci = r % 44;
        cta_params(ci, nj, j0);
    }

    const uint4* wp4;
    if (layer == 0)
        wp4 = (const uint4*)g_wA0 + ((size_t)(cta * 16 + wid)) * 1024 + lane;
    else
        wp4 = (const uint4*)g_wAca + ((size_t)(((layer - 1) * 44 + ci) * 16 + wid)) * 1024 + lane;

    for (int t = 0; t < Tsz; ++t) {
        // ---- wait for producers ----
        if (tid == 0) {
            if (layer == 0) {
                if (t > 0) {
                    volatile unsigned* p = &g_done[0];
                    while (*p < 16u * (unsigned)t) { }
                }
            } else {
                unsigned needl = (layer == 1 ? 16u : 44u) * (unsigned)(t + 1);
                volatile unsigned* pl = &g_done[layer - 1];
                while (*pl < needl) { }
                if (t > 0) {
                    volatile unsigned* po = &g_done[layer];
                    while (*po < 44u * (unsigned)t) { }
                }
            }
            __threadfence();
        }
        __syncthreads();

        // ---- tensor-core GEMM with fragment-direct B loads ----
        if (layer == 0) {
            float d[8][4] = {};
            if (t > 0) {
                const uint* hb = g_fhi + ((size_t)(t - 1)) * 8192 + lanepart;
                const uint* lb = g_flo + ((size_t)(t - 1)) * 8192 + lanepart;
                #pragma unroll 1
                for (int ks = 0; ks < 8; ks++) {
                    uint4 ah0 = __ldg(wp4 + ((ks * 2 + 0) * 2 + 0) * 32);
                    uint4 al0 = __ldg(wp4 + ((ks * 2 + 0) * 2 + 1) * 32);
                    uint4 ah1 = __ldg(wp4 + ((ks * 2 + 1) * 2 + 0) * 32);
                    uint4 al1 = __ldg(wp4 + ((ks * 2 + 1) * 2 + 1) * 32);
                    int to = (kw * 8 + ks) * 256;
                    uint4 b0h = __ldcg((const uint4*)(hb + to));
                    uint4 b1h = __ldcg((const uint4*)(hb + to + 128));
                    uint4 b0l = __ldcg((const uint4*)(lb + to));
                    uint4 b1l = __ldcg((const uint4*)(lb + to + 128));
                    #define DO_NT(NT, X) { \
                        mma_bf16(d[NT],     ah0, b0h.X, b1h.X); \
                        mma_bf16(d[NT],     ah0, b0l.X, b1l.X); \
                        mma_bf16(d[NT],     al0, b0h.X, b1h.X); \
                        mma_bf16(d[4+NT],   ah1, b0h.X, b1h.X); \
                        mma_bf16(d[4+NT],   ah1, b0l.X, b1l.X); \
                        mma_bf16(d[4+NT],   al1, b0h.X, b1h.X); }
                    DO_NT(0, x) DO_NT(1, y) DO_NT(2, z) DO_NT(3, w)
                    #undef DO_NT
                }
            }
            float* pp = part + kw * PSTR;
            #pragma unroll
            for (int mt = 0; mt < 2; mt++)
                #pragma unroll
                for (int nt = 0; nt < 4; nt++) {
                    int sl0 = mw * 32 + mt * 16 + gr;
                    int bc = nt * 8 + c0;
                    float* dd = d[mt * 4 + nt];
                    pp[sl0 * 33 + bc] = dd[0];       pp[sl0 * 33 + bc + 1] = dd[1];
                    pp[(sl0 + 8) * 33 + bc] = dd[2]; pp[(sl0 + 8) * 33 + bc + 1] = dd[3];
                }
        } else {
            float d[4][4] = {};
            bool skip = (t == 0 && kw >= 2);
            if (!skip) {
                size_t blk;
                int tile0;
                if (kw < 2) { blk = ((size_t)(layer - 1) * Tsz + t) * 8192;       tile0 = kw * 16; }
                else        { blk = ((size_t)layer * Tsz + (t - 1)) * 8192;       tile0 = kw * 16 - 32; }
                const uint* hb = g_fhi + blk + lanepart;
                const uint* lb = g_flo + blk + lanepart;
                #pragma unroll 2
                for (int ks = 0; ks < 16; ks++) {
                    uint4 ah = __ldg(wp4 + (ks * 2 + 0) * 32);
                    uint4 al = __ldg(wp4 + (ks * 2 + 1) * 32);
                    int to = (tile0 + ks) * 256;
                    uint4 b0h = __ldcg((const uint4*)(hb + to));
                    uint4 b1h = __ldcg((const uint4*)(hb + to + 128));
                    uint4 b0l = __ldcg((const uint4*)(lb + to));
                    uint4 b1l = __ldcg((const uint4*)(lb + to + 128));
                    #define DO_NT(NT, X) { \
                        mma_bf16(d[NT], ah, b0h.X, b1h.X); \
                        mma_bf16(d[NT], ah, b0l.X, b1l.X); \
                        mma_bf16(d[NT], al, b0h.X, b1h.X); }
                    DO_NT(0, x) DO_NT(1, y) DO_NT(2, z) DO_NT(3, w)
                    #undef DO_NT
                }
            }
            float* pp = part + kw * PSTR;
            #pragma unroll
            for (int nt = 0; nt < 4; nt++) {
                int sl0 = mw * 16 + gr;
                int bc = nt * 8 + c0;
                pp[sl0 * 33 + bc] = d[nt][0];       pp[sl0 * 33 + bc + 1] = d[nt][1];
                pp[(sl0 + 8) * 33 + bc] = d[nt][2]; pp[(sl0 + 8) * 33 + bc + 1] = d[nt][3];
            }
        }
        __syncthreads();

        // ---- merged reduce + activation + state update + fragment store ----
        {
            size_t so = (((size_t)layer * Tsz + t)) * 32;
            float* cout = g_c + so * 512;
            ushort* fh = (ushort*)(g_fhi + ((size_t)layer * Tsz + t) * 8192);
            ushort* fl = (ushort*)(g_flo + ((size_t)layer * Tsz + t) * 8192);
            const float* cprev = (t > 0) ? g_c + (((size_t)layer * Tsz + (t - 1)) * 32) * 512 : nullptr;
            #define RED(SL, B) (part[(SL) * 33 + (B)] + part[PSTR + (SL) * 33 + (B)] \
                              + part[2 * PSTR + (SL) * 33 + (B)] + part[3 * PSTR + (SL) * 33 + (B)])
            if (layer == 0) {
                const float* xb = g_xt + ((size_t)t * 2048 + cta * 128) * 32;
                for (int it = tid; it < 1024; it += NTHR) {
                    int b = it >> 5, jj = it & 31;
                    int j = cta * 32 + jj;
                    float i_ = RED(0 * 32 + jj, b) + __ldcg(xb + (0 * 32 + jj) * 32 + b);
                    float f_ = RED(1 * 32 + jj, b) + __ldcg(xb + (1 * 32 + jj) * 32 + b);
                    float gg = RED(2 * 32 + jj, b) + __ldcg(xb + (2 * 32 + jj) * 32 + b);
                    float o_ = RED(3 * 32 + jj, b) + __ldcg(xb + (3 * 32 + jj) * 32 + b);
                    float cp = cprev ? __ldcg(cprev + (size_t)b * 512 + j) : 0.0f;
                    float cv = sigf(i_) * tanhf(gg) + sigf(f_) * cp;
                    float hv = sigf(o_) * tanhf(cv);
                    cout[(size_t)b * 512 + j] = cv;
                    ushort uh = bfhi(hv);
                    float hf2 = __bfloat162float(__ushort_as_bfloat16(uh));
                    int fi = frag_idx(j, b) * 2 + (j & 1);
                    fh[fi] = uh;
                    fl[fi] = bfhi(hv - hf2);
                }
            } else {
                const float* clow = g_c + (((size_t)(layer - 1) * Tsz + t) * 32) * 512;
                const float* cb = ca_b + (size_t)(layer - 1) * G5;
                for (int it = tid; it < nj * 32; it += NTHR) {
                    int b = it / nj, jj = it - b * nj;
                    int j = j0 + jj;
                    float i_ = RED(0 * nj + jj, b) + cb[0 * 512 + j];
                    float fp = RED(1 * nj + jj, b) + cb[1 * 512 + j];
                    float fl_ = RED(2 * nj + jj, b) + cb[2 * 512 + j];
                    float u_ = RED(3 * nj + jj, b) + cb[3 * 512 + j];
                    float o_ = RED(4 * nj + jj, b) + cb[4 * 512 + j];
                    float cp = cprev ? __ldcg(cprev + (size_t)b * 512 + j) : 0.0f;
                    float cl = __ldcg(clow + (size_t)b * 512 + j);
                    float cv = cp * sigf(fp + 1.0f) + cl * sigf(fl_ + 1.0f) + tanhf(u_) * sigf(i_);
                    float hv = sigf(o_) * tanhf(cv);
                    cout[(size_t)b * 512 + j] = cv;
                    ushort uh = bfhi(hv);
                    float hf2 = __bfloat162float(__ushort_as_bfloat16(uh));
                    int fi = frag_idx(j, b) * 2 + (j & 1);
                    fh[fi] = uh;
                    fl[fi] = bfhi(hv - hf2);
                    if (layer == 3) {
                        out[(size_t)b * Tsz * Hsz + (size_t)t * Hsz + j] = hv;
                        out[BTHn + (size_t)b * Tsz * Hsz + (size_t)t * Hsz + j] = cv;
                        if (t == Tsz - 1) {
                            out[2 * BTHn + (size_t)b * Hsz + j] = hv;
                            out[2 * BTHn + (size_t)Bsz * Hsz + (size_t)b * Hsz + j] = cv;
                        }
                    }
                }
            }
            #undef RED
        }
        __syncthreads();

        // ---- publish completion of step t ----
        if (tid == 0) {
            __threadfence();
            atomicAdd(&g_done[layer], 1u);
        }
    }
}

extern "C" void kernel_launch(void* const* d_in, const int* in_sizes, int n_in,
                              void* d_out, int out_size)
{
    const float* x    = (const float*)d_in[0];
    const float* w_ih = (const float*)d_in[1];
    const float* w_hh = (const float*)d_in[2];
    const float* b_ih = (const float*)d_in[3];
    const float* b_hh = (const float*)d_in[4];
    const float* ca_w = (const float*)d_in[5];
    const float* ca_b = (const float*)d_in[6];
    float* out = (float*)d_out;
    (void)in_sizes; (void)n_in; (void)out_size;

    k_fill<<<296, 256>>>(w_hh, ca_w);

    dim3 g(G4 / 64, (Tsz * Bsz) / 64);
    k_xproj<<<g, 256>>>(x, w_ih, b_ih, b_hh);

    const int smem_bytes = 4 * PSTR * 4;  // 67584
    cudaFuncSetAttribute(k_wave, cudaFuncAttributeMaxDynamicSharedMemorySize, smem_bytes);
    k_wave<<<NCTA, NTHR, smem_bytes>>>(ca_b, out);
}

// round 9
// speedup vs baseline: 1.3764x; 1.3764x over previous
#include <cuda_runtime.h>
#include <cuda_fp16.h>
#include <cstdint>
#include <math.h>

#define Bsz 32
#define Tsz 512
#define DIsz 512
#define Hsz 512
#define G4 2048
#define G5 2560
#define NCTA 148
#define NTHR 512
#define BTHn ((size_t)32*512*512)

typedef unsigned int uint;
typedef unsigned short ushort;

// ---- static device scratch ----
// h stored as ONE fp16, layout [layer][t][b][k]; c fp32 [layer][t][b][j]
static __device__ __align__(16) ushort g_hh[(size_t)4*512*32*512];
static __device__ float g_c[(size_t)4*512*32*512];
static __device__ float g_xt[(size_t)512*2048*32];           // [t][rowp][b]
// weights pre-packed in mma-fragment order (fp16x2 per uint), part0=hi, part1=lo
static __device__ __align__(16) uint g_wA0[(size_t)16*16*32*128];    // L0 frags
static __device__ __align__(16) uint g_wAca[(size_t)132*16*32*128];  // CA frags
static __device__ unsigned g_done[4];                        // per-layer step counters

#define PSTR 4224            // 128*33 floats per kw partial region
#define PART_OFF 66048       // bytes: B region = 32*1032 ushorts * 2B

__device__ __forceinline__ float sigf(float x) { return 1.0f / (1.0f + __expf(-x)); }

__device__ __forceinline__ ushort f16hi(float w) {
    return __half_as_ushort(__float2half_rn(w));
}
__device__ __forceinline__ ushort f16lo(float w) {
    float h = __half2float(__float2half_rn(w));
    return __half_as_ushort(__float2half_rn(w - h));
}

__device__ __forceinline__ void mma_f16(float* d, const uint4& a, uint b0, uint b1) {
    asm volatile(
        "mma.sync.aligned.m16n8k16.row.col.f32.f16.f16.f32 "
        "{%0,%1,%2,%3},{%4,%5,%6,%7},{%8,%9},{%0,%1,%2,%3};"
        : "+f"(d[0]), "+f"(d[1]), "+f"(d[2]), "+f"(d[3])
        : "r"(a.x), "r"(a.y), "r"(a.z), "r"(a.w), "r"(b0), "r"(b1));
}

static __device__ __host__ __forceinline__ void cta_params(int ci, int& nj, int& j0) {
    if (ci < 28) { nj = 12; j0 = ci * 12; }
    else         { nj = 11; j0 = 336 + (ci - 28) * 11; }
}

// ---------------- weight fragment packing + counter reset ----------------
__global__ void __launch_bounds__(256) k_fill(const float* __restrict__ w_hh,
                                              const float* __restrict__ ca_w)
{
    size_t stride = (size_t)gridDim.x * blockDim.x;
    size_t i0 = (size_t)blockIdx.x * blockDim.x + threadIdx.x;
    if (i0 < 4) g_done[i0] = 0u;

    const size_t N0 = (size_t)16*16*32*128;
    for (size_t e = i0; e < N0; e += stride) {
        int reg = (int)(e & 3), lane = (int)((e >> 2) & 31), f = (int)((e >> 7) & 31);
        int wid = (int)((e >> 12) & 15), cta = (int)(e >> 16);
        int part = f & 1, mt = (f >> 1) & 1, ks = f >> 2;
        int mw = wid >> 2, kw = wid & 3;
        int gr = lane >> 2, c0 = (lane & 3) * 2;
        int slot = mw * 32 + mt * 16 + gr + (reg & 1) * 8;
        int kk = kw * 128 + ks * 16 + c0 + ((reg >> 1) & 1) * 8;
        int row = (slot >> 5) * 512 + cta * 32 + (slot & 31);
        float w0 = w_hh[(size_t)row * 512 + kk];
        float w1 = w_hh[(size_t)row * 512 + kk + 1];
        ushort u0 = part ? f16lo(w0) : f16hi(w0);
        ushort u1 = part ? f16lo(w1) : f16hi(w1);
        g_wA0[e] = (uint)u0 | ((uint)u1 << 16);
    }
    const size_t NC = (size_t)132*16*32*128;
    for (size_t e = i0; e < NC; e += stride) {
        int reg = (int)(e & 3), lane = (int)((e >> 2) & 31), f = (int)((e >> 7) & 31);
        int wid = (int)((e >> 12) & 15), lc = (int)(e >> 16);
        int part = f & 1, ks = f >> 1;
        int mw = wid >> 2, kw = wid & 3;
        int gr = lane >> 2, c0 = (lane & 3) * 2;
        int slot = mw * 16 + gr + (reg & 1) * 8;
        int kk = kw * 256 + ks * 16 + c0 + ((reg >> 1) & 1) * 8;
        int ci = lc % 44, l = lc / 44;
        int nj, j0; cta_params(ci, nj, j0);
        float w0 = 0.0f, w1 = 0.0f;
        if (slot < 5 * nj) {
            int g = slot / nj, jj = slot - g * nj;
            int row = g * 512 + j0 + jj;
            w0 = ca_w[((size_t)l * G5 + row) * 1024 + kk];
            w1 = ca_w[((size_t)l * G5 + row) * 1024 + kk + 1];
        }
        ushort u0 = part ? f16lo(w0) : f16hi(w0);
        ushort u1 = part ? f16lo(w1) : f16hi(w1);
        g_wAca[e] = (uint)u0 | ((uint)u1 << 16);
    }
}

// ---------------- xproj = x @ w_ih.T + bias, stored [t][rowp][b] ----------------
__global__ void __launch_bounds__(256) k_xproj(
    const float* __restrict__ x, const float* __restrict__ w_ih,
    const float* __restrict__ b_ih, const float* __restrict__ b_hh)
{
    __shared__ float As[16][65];
    __shared__ float Bs[16][65];
    const int bm = blockIdx.y * 64, bn = blockIdx.x * 64;
    const int tid = threadIdx.x;
    const int tr = (tid >> 4) << 2, tc = (tid & 15) << 2;
    float acc[4][4] = {};
    for (int k0 = 0; k0 < DIsz; k0 += 16) {
        #pragma unroll
        for (int i0 = 0; i0 < 4; i0++) {
            int i = i0 * 256 + tid;
            int mm = i >> 4, kk = i & 15;
            int m = bm + mm, tt = m >> 5, bb = m & 31;
            As[kk][mm] = x[((size_t)bb * Tsz + tt) * DIsz + (k0 + kk)];
            Bs[kk][mm] = w_ih[(size_t)(bn + mm) * DIsz + (k0 + kk)];
        }
        __syncthreads();
        #pragma unroll
        for (int kk = 0; kk < 16; kk++) {
            float a[4] = {As[kk][tr], As[kk][tr+1], As[kk][tr+2], As[kk][tr+3]};
            float b[4] = {Bs[kk][tc], Bs[kk][tc+1], Bs[kk][tc+2], Bs[kk][tc+3]};
            #pragma unroll
            for (int i = 0; i < 4; i++)
                #pragma unroll
                for (int j = 0; j < 4; j++)
                    acc[i][j] = fmaf(a[i], b[j], acc[i][j]);
        }
        __syncthreads();
    }
    #pragma unroll
    for (int i = 0; i < 4; i++) {
        int m = bm + tr + i, tt = m >> 5, bb = m & 31;
        #pragma unroll
        for (int j = 0; j < 4; j++) {
            int n = bn + tc + j;
            int g = n >> 9, cd = (n >> 5) & 15, jj = n & 31;
            g_xt[((size_t)tt * 2048 + cd * 128 + g * 32 + jj) * 32 + bb]
                = acc[i][j] + b_ih[n] + b_hh[n];
        }
    }
}

// ---------------- persistent self-timed LSTM, fp16 2-MMA tensor GEMM ----------------
__global__ void __launch_bounds__(NTHR, 1) k_wave(
    const float* __restrict__ ca_b, float* __restrict__ out)
{
    extern __shared__ char smx[];

    const int tid  = threadIdx.x;
    const int lane = tid & 31;
    const int wid  = tid >> 5;
    const int cta  = blockIdx.x;
    const int mw = wid >> 2, kw = wid & 3;
    const int gr = lane >> 2, c0 = (lane & 3) * 2;

    int layer, j0, nj, ci = 0;
    if (cta < 16) { layer = 0; nj = 32; j0 = cta * 32; }
    else {
        int r = cta - 16;
        layer = 1 + r / 44;
        ci = r % 44;
        cta_params(ci, nj, j0);
    }
    const int K  = (layer == 0) ? 512 : 1024;
    const int rs = K + 8;
    ushort* Bh = (ushort*)smx;
    float* part = (float*)(smx + PART_OFF);

    const uint4* wp4;
    if (layer == 0)
        wp4 = (const uint4*)g_wA0 + ((size_t)(cta * 16 + wid)) * 1024 + lane;
    else
        wp4 = (const uint4*)g_wAca + ((size_t)(((layer - 1) * 44 + ci) * 16 + wid)) * 1024 + lane;

    const int nch = K >> 3;            // uint4 chunks per B row
    const int chsh = (layer == 0) ? 6 : 7;

    for (int t = 0; t < Tsz; ++t) {
        // ---- wait for producers ----
        if (tid == 0) {
            if (layer == 0) {
                if (t > 0) {
                    volatile unsigned* p = &g_done[0];
                    while (*p < 16u * (unsigned)t) { }
                }
            } else {
                unsigned needl = (layer == 1 ? 16u : 44u) * (unsigned)(t + 1);
                volatile unsigned* pl = &g_done[layer - 1];
                while (*pl < needl) { }
                if (t > 0) {
                    volatile unsigned* po = &g_done[layer];
                    while (*po < 44u * (unsigned)t) { }
                }
            }
            __threadfence();
        }
        __syncthreads();

        // ---- stage H (fp16) into smem [b][k] ----
        {
            const uint4 zz = make_uint4(0, 0, 0, 0);
            for (int e = tid; e < 32 * nch; e += NTHR) {
                int b = e >> chsh, c = e & (nch - 1);
                int k8 = c * 8;
                const ushort* sh = nullptr;
                if (layer == 0) {
                    if (t > 0)
                        sh = g_hh + (((size_t)(t - 1)) * 32 + b) * 512 + k8;
                } else {
                    if (k8 < 512)
                        sh = g_hh + (((size_t)(layer - 1) * Tsz + t) * 32 + b) * 512 + k8;
                    else if (t > 0)
                        sh = g_hh + (((size_t)layer * Tsz + (t - 1)) * 32 + b) * 512 + (k8 - 512);
                }
                uint4 vh = sh ? __ldcg((const uint4*)sh) : zz;
                *(uint4*)(Bh + b * rs + k8) = vh;
            }
        }
        __syncthreads();

        // ---- tensor-core GEMM (weights prefetched one ks ahead) ----
        if (layer == 0) {
            float d[8][4] = {};
            const int kb = kw * 128 + c0;
            uint4 ah0 = __ldg(wp4 + 0 * 32), al0 = __ldg(wp4 + 1 * 32);
            uint4 ah1 = __ldg(wp4 + 2 * 32), al1 = __ldg(wp4 + 3 * 32);
            #pragma unroll
            for (int ks = 0; ks < 8; ks++) {
                uint4 nh0 = ah0, nl0 = al0, nh1 = ah1, nl1 = al1;
                if (ks < 7) {
                    nh0 = __ldg(wp4 + (((ks + 1) * 2 + 0) * 2 + 0) * 32);
                    nl0 = __ldg(wp4 + (((ks + 1) * 2 + 0) * 2 + 1) * 32);
                    nh1 = __ldg(wp4 + (((ks + 1) * 2 + 1) * 2 + 0) * 32);
                    nl1 = __ldg(wp4 + (((ks + 1) * 2 + 1) * 2 + 1) * 32);
                }
                int k = kb + ks * 16;
                #pragma unroll
                for (int nt = 0; nt < 4; nt++) {
                    const ushort* ph = Bh + (nt * 8 + gr) * rs + k;
                    uint bh0 = *(const uint*)ph, bh1 = *(const uint*)(ph + 8);
                    mma_f16(d[nt],     ah0, bh0, bh1);
                    mma_f16(d[nt],     al0, bh0, bh1);
                    mma_f16(d[4 + nt], ah1, bh0, bh1);
                    mma_f16(d[4 + nt], al1, bh0, bh1);
                }
                ah0 = nh0; al0 = nl0; ah1 = nh1; al1 = nl1;
            }
            float* pp = part + kw * PSTR;
            #pragma unroll
            for (int mt = 0; mt < 2; mt++)
                #pragma unroll
                for (int nt = 0; nt < 4; nt++) {
                    int sl0 = mw * 32 + mt * 16 + gr;
                    int bc = nt * 8 + c0;
                    float* dd = d[mt * 4 + nt];
                    pp[sl0 * 33 + bc] = dd[0];       pp[sl0 * 33 + bc + 1] = dd[1];
                    pp[(sl0 + 8) * 33 + bc] = dd[2]; pp[(sl0 + 8) * 33 + bc + 1] = dd[3];
                }
        } else {
            float d[4][4] = {};
            const int kb = kw * 256 + c0;
            uint4 ah = __ldg(wp4 + 0 * 32), al = __ldg(wp4 + 1 * 32);
            #pragma unroll
            for (int ks = 0; ks < 16; ks++) {
                uint4 nh = ah, nl = al;
                if (ks < 15) {
                    nh = __ldg(wp4 + ((ks + 1) * 2 + 0) * 32);
                    nl = __ldg(wp4 + ((ks + 1) * 2 + 1) * 32);
                }
                int k = kb + ks * 16;
                #pragma unroll
                for (int nt = 0; nt < 4; nt++) {
                    const ushort* ph = Bh + (nt * 8 + gr) * rs + k;
                    uint bh0 = *(const uint*)ph, bh1 = *(const uint*)(ph + 8);
                    mma_f16(d[nt], ah, bh0, bh1);
                    mma_f16(d[nt], al, bh0, bh1);
                }
                ah = nh; al = nl;
            }
            float* pp = part + kw * PSTR;
            #pragma unroll
            for (int nt = 0; nt < 4; nt++) {
                int sl0 = mw * 16 + gr;
                int bc = nt * 8 + c0;
                pp[sl0 * 33 + bc] = d[nt][0];       pp[sl0 * 33 + bc + 1] = d[nt][1];
                pp[(sl0 + 8) * 33 + bc] = d[nt][2]; pp[(sl0 + 8) * 33 + bc + 1] = d[nt][3];
            }
        }
        __syncthreads();

        // ---- merged reduce + activation + state update ----
        {
            size_t so = (((size_t)layer * Tsz + t)) * 32;
            float*  cout = g_c  + so * 512;
            ushort* hho  = g_hh + so * 512;
            const float* cprev = (t > 0) ? g_c + (((size_t)layer * Tsz + (t - 1)) * 32) * 512 : nullptr;
            #define RED(SL, B) (part[(SL) * 33 + (B)] + part[PSTR + (SL) * 33 + (B)] \
                              + part[2 * PSTR + (SL) * 33 + (B)] + part[3 * PSTR + (SL) * 33 + (B)])
            if (layer == 0) {
                const float* xb = g_xt + ((size_t)t * 2048 + cta * 128) * 32;
                for (int it = tid; it < 1024; it += NTHR) {
                    int b = it >> 5, jj = it & 31;
                    int j = cta * 32 + jj;
                    float i_ = RED(0 * 32 + jj, b) + __ldcg(xb + (0 * 32 + jj) * 32 + b);
                    float f_ = RED(1 * 32 + jj, b) + __ldcg(xb + (1 * 32 + jj) * 32 + b);
                    float gg = RED(2 * 32 + jj, b) + __ldcg(xb + (2 * 32 + jj) * 32 + b);
                    float o_ = RED(3 * 32 + jj, b) + __ldcg(xb + (3 * 32 + jj) * 32 + b);
                    float cp = cprev ? __ldcg(cprev + (size_t)b * 512 + j) : 0.0f;
                    float cv = sigf(i_) * tanhf(gg) + sigf(f_) * cp;
                    float hv = sigf(o_) * tanhf(cv);
                    cout[(size_t)b * 512 + j] = cv;
                    hho[(size_t)b * 512 + j]  = __half_as_ushort(__float2half_rn(hv));
                }
            } else {
                const float* clow = g_c + (((size_t)(layer - 1) * Tsz + t) * 32) * 512;
                const float* cb = ca_b + (size_t)(layer - 1) * G5;
                for (int it = tid; it < nj * 32; it += NTHR) {
                    int b = it / nj, jj = it - b * nj;
                    int j = j0 + jj;
                    float i_ = RED(0 * nj + jj, b) + cb[0 * 512 + j];
                    float fp = RED(1 * nj + jj, b) + cb[1 * 512 + j];
                    float fl = RED(2 * nj + jj, b) + cb[2 * 512 + j];
                    float u_ = RED(3 * nj + jj, b) + cb[3 * 512 + j];
                    float o_ = RED(4 * nj + jj, b) + cb[4 * 512 + j];
                    float cp = cprev ? __ldcg(cprev + (size_t)b * 512 + j) : 0.0f;
                    float cl = __ldcg(clow + (size_t)b * 512 + j);
                    float cv = cp * sigf(fp + 1.0f) + cl * sigf(fl + 1.0f) + tanhf(u_) * sigf(i_);
                    float hv = sigf(o_) * tanhf(cv);
                    cout[(size_t)b * 512 + j] = cv;
                    hho[(size_t)b * 512 + j]  = __half_as_ushort(__float2half_rn(hv));
                    if (layer == 3) {
                        out[(size_t)b * Tsz * Hsz + (size_t)t * Hsz + j] = hv;
                        out[BTHn + (size_t)b * Tsz * Hsz + (size_t)t * Hsz + j] = cv;
                        if (t == Tsz - 1) {
                            out[2 * BTHn + (size_t)b * Hsz + j] = hv;
                            out[2 * BTHn + (size_t)Bsz * Hsz + (size_t)b * Hsz + j] = cv;
                        }
                    }
                }
            }
            #undef RED
        }
        __syncthreads();

        // ---- publish completion of step t ----
        if (tid == 0) {
            __threadfence();
            atomicAdd(&g_done[layer], 1u);
        }
    }
}

extern "C" void kernel_launch(void* const* d_in, const int* in_sizes, int n_in,
                              void* d_out, int out_size)
{
    const float* x    = (const float*)d_in[0];
    const float* w_ih = (const float*)d_in[1];
    const float* w_hh = (const float*)d_in[2];
    const float* b_ih = (const float*)d_in[3];
    const float* b_hh = (const float*)d_in[4];
    const float* ca_w = (const float*)d_in[5];
    const float* ca_b = (const float*)d_in[6];
    float* out = (float*)d_out;
    (void)in_sizes; (void)n_in; (void)out_size;

    k_fill<<<296, 256>>>(w_hh, ca_w);

    dim3 g(G4 / 64, (Tsz * Bsz) / 64);
    k_xproj<<<g, 256>>>(x, w_ih, b_ih, b_hh);

    const int smem_bytes = PART_OFF + 4 * PSTR * 4;  // 66048 + 67584 = 133632
    cudaFuncSetAttribute(k_wave, cudaFuncAttributeMaxDynamicSharedMemorySize, smem_bytes);
    k_wave<<<NCTA, NTHR, smem_bytes>>>(ca_b, out);
}

// round 10
// speedup vs baseline: 1.5474x; 1.1242x over previous
#include <cuda_runtime.h>
#include <cuda_fp16.h>
#include <cstdint>
#include <math.h>

#define Bsz 32
#define Tsz 512
#define DIsz 512
#define Hsz 512
#define G4 2048
#define G5 2560
#define NCTA 148
#define NTHR 512
#define BTHn ((size_t)32*512*512)

typedef unsigned int uint;
typedef unsigned short ushort;

// ---- static device scratch ----
// h stored as ONE fp16, layout [layer][t][b][k]; c fp32 [layer][t][b][j]
static __device__ __align__(16) ushort g_hh[(size_t)4*512*32*512];
static __device__ float g_c[(size_t)4*512*32*512];
static __device__ float g_xt[(size_t)512*2048*32];           // [t][rowp][b]
// single-fp16 weights in mma A-fragment order, deduped per (block, mtile[,kw])
static __device__ __align__(16) uint g_wA0[(size_t)16*8*32*128];     // L0: [cta][mw][ks][lane*4+reg]
static __device__ __align__(16) uint g_wAca[(size_t)132*8*32*128];   // CA: [lc][mw*2+kw][ks][...]
static __device__ unsigned g_done[4];                        // per-layer step counters

#define PSTR 4224            // 128*33 floats per partial region
#define PART_OFF 66048       // bytes: B region = 32*1032 ushorts * 2B

// fast activations (MUFU-based, ~1e-7 error, correct saturation)
__device__ __forceinline__ float sigf(float x) {
    return __fdividef(1.0f, 1.0f + __expf(-x));
}
__device__ __forceinline__ float tanhef(float x) {
    return __fdividef(2.0f, 1.0f + __expf(-2.0f * x)) - 1.0f;
}

__device__ __forceinline__ ushort f16of(float w) {
    return __half_as_ushort(__float2half_rn(w));
}

__device__ __forceinline__ void mma_f16(float* d, const uint4& a, uint b0, uint b1) {
    asm volatile(
        "mma.sync.aligned.m16n8k16.row.col.f32.f16.f16.f32 "
        "{%0,%1,%2,%3},{%4,%5,%6,%7},{%8,%9},{%0,%1,%2,%3};"
        : "+f"(d[0]), "+f"(d[1]), "+f"(d[2]), "+f"(d[3])
        : "r"(a.x), "r"(a.y), "r"(a.z), "r"(a.w), "r"(b0), "r"(b1));
}

static __device__ __host__ __forceinline__ void cta_params(int ci, int& nj, int& j0) {
    if (ci < 28) { nj = 12; j0 = ci * 12; }
    else         { nj = 11; j0 = 336 + (ci - 28) * 11; }
}

// ---------------- weight fragment packing + counter reset ----------------
__global__ void __launch_bounds__(256) k_fill(const float* __restrict__ w_hh,
                                              const float* __restrict__ ca_w)
{
    size_t stride = (size_t)gridDim.x * blockDim.x;
    size_t i0 = (size_t)blockIdx.x * blockDim.x + threadIdx.x;
    if (i0 < 4) g_done[i0] = 0u;

    // L0: e = ((cta*8 + mw)*32 + ks)*128 + lane*4 + reg ; K full 512 per region
    const size_t N0 = (size_t)16*8*32*128;
    for (size_t e = i0; e < N0; e += stride) {
        int reg = (int)(e & 3), lane = (int)((e >> 2) & 31), ks = (int)((e >> 7) & 31);
        int mw = (int)((e >> 12) & 7), cta = (int)(e >> 15);
        int gr = lane >> 2, c0 = (lane & 3) * 2;
        int slot = mw * 16 + gr + (reg & 1) * 8;                 // 0..127
        int kk = ks * 16 + c0 + ((reg >> 1) & 1) * 8;            // 0..511
        int row = (slot >> 5) * 512 + cta * 32 + (slot & 31);
        float w0 = w_hh[(size_t)row * 512 + kk];
        float w1 = w_hh[(size_t)row * 512 + kk + 1];
        g_wA0[e] = (uint)f16of(w0) | ((uint)f16of(w1) << 16);
    }
    // CA: e = ((lc*8 + mw*2+kw)*32 + ks)*128 + lane*4 + reg ; K half (512) per region
    const size_t NC = (size_t)132*8*32*128;
    for (size_t e = i0; e < NC; e += stride) {
        int reg = (int)(e & 3), lane = (int)((e >> 2) & 31), ks = (int)((e >> 7) & 31);
        int mk = (int)((e >> 12) & 7), lc = (int)(e >> 15);
        int mw = mk >> 1, kw = mk & 1;
        int gr = lane >> 2, c0 = (lane & 3) * 2;
        int slot = mw * 16 + gr + (reg & 1) * 8;                 // 0..63
        int kk = kw * 512 + ks * 16 + c0 + ((reg >> 1) & 1) * 8; // 0..1023
        int ci = lc % 44, l = lc / 44;
        int nj, j0; cta_params(ci, nj, j0);
        float w0 = 0.0f, w1 = 0.0f;
        if (slot < 5 * nj) {
            int g = slot / nj, jj = slot - g * nj;
            int row = g * 512 + j0 + jj;
            w0 = ca_w[((size_t)l * G5 + row) * 1024 + kk];
            w1 = ca_w[((size_t)l * G5 + row) * 1024 + kk + 1];
        }
        g_wAca[e] = (uint)f16of(w0) | ((uint)f16of(w1) << 16);
    }
}

// ---------------- xproj = x @ w_ih.T + bias, stored [t][rowp][b] ----------------
__global__ void __launch_bounds__(256) k_xproj(
    const float* __restrict__ x, const float* __restrict__ w_ih,
    const float* __restrict__ b_ih, const float* __restrict__ b_hh)
{
    __shared__ float As[16][65];
    __shared__ float Bs[16][65];
    const int bm = blockIdx.y * 64, bn = blockIdx.x * 64;
    const int tid = threadIdx.x;
    const int tr = (tid >> 4) << 2, tc = (tid & 15) << 2;
    float acc[4][4] = {};
    for (int k0 = 0; k0 < DIsz; k0 += 16) {
        #pragma unroll
        for (int i0 = 0; i0 < 4; i0++) {
            int i = i0 * 256 + tid;
            int mm = i >> 4, kk = i & 15;
            int m = bm + mm, tt = m >> 5, bb = m & 31;
            As[kk][mm] = x[((size_t)bb * Tsz + tt) * DIsz + (k0 + kk)];
            Bs[kk][mm] = w_ih[(size_t)(bn + mm) * DIsz + (k0 + kk)];
        }
        __syncthreads();
        #pragma unroll
        for (int kk = 0; kk < 16; kk++) {
            float a[4] = {As[kk][tr], As[kk][tr+1], As[kk][tr+2], As[kk][tr+3]};
            float b[4] = {Bs[kk][tc], Bs[kk][tc+1], Bs[kk][tc+2], Bs[kk][tc+3]};
            #pragma unroll
            for (int i = 0; i < 4; i++)
                #pragma unroll
                for (int j = 0; j < 4; j++)
                    acc[i][j] = fmaf(a[i], b[j], acc[i][j]);
        }
        __syncthreads();
    }
    #pragma unroll
    for (int i = 0; i < 4; i++) {
        int m = bm + tr + i, tt = m >> 5, bb = m & 31;
        #pragma unroll
        for (int j = 0; j < 4; j++) {
            int n = bn + tc + j;
            int g = n >> 9, cd = (n >> 5) & 15, jj = n & 31;
            g_xt[((size_t)tt * 2048 + cd * 128 + g * 32 + jj) * 32 + bb]
                = acc[i][j] + b_ih[n] + b_hh[n];
        }
    }
}

// ---------------- persistent self-timed LSTM, fp16 1-MMA tensor GEMM ----------------
__global__ void __launch_bounds__(NTHR, 1) k_wave(
    const float* __restrict__ ca_b, float* __restrict__ out)
{
    extern __shared__ char smx[];

    const int tid  = threadIdx.x;
    const int lane = tid & 31;
    const int wid  = tid >> 5;
    const int cta  = blockIdx.x;
    const int gr = lane >> 2, c0 = (lane & 3) * 2;

    int layer, j0, nj, ci = 0;
    if (cta < 16) { layer = 0; nj = 32; j0 = cta * 32; }
    else {
        int r = cta - 16;
        layer = 1 + r / 44;
        ci = r % 44;
        cta_params(ci, nj, j0);
    }
    const int K  = (layer == 0) ? 512 : 1024;
    const int rs = K + 8;
    ushort* Bh = (ushort*)smx;
    float* part = (float*)(smx + PART_OFF);

    // warp roles: L0: mw=wid>>1 (0..7), np=wid&1, kw=0 (full K)
    //             CA: mw=wid>>2 (0..3), np=(wid>>1)&1, kw=wid&1 (K halves)
    int mw, np, kw;
    const uint4* wp4;
    if (layer == 0) {
        mw = wid >> 1; np = wid & 1; kw = 0;
        wp4 = (const uint4*)g_wA0 + ((size_t)(cta * 8 + mw)) * 1024 + lane;
    } else {
        mw = wid >> 2; np = (wid >> 1) & 1; kw = wid & 1;
        wp4 = (const uint4*)g_wAca + ((size_t)(((layer - 1) * 44 + ci) * 8 + mw * 2 + kw)) * 1024 + lane;
    }
    const int kB = kw * 512 + c0;

    const int nch = K >> 3;            // uint4 chunks per B row
    const int chsh = (layer == 0) ? 6 : 7;

    for (int t = 0; t < Tsz; ++t) {
        // ---- wait for producers ----
        if (tid == 0) {
            if (layer == 0) {
                if (t > 0) {
                    volatile unsigned* p = &g_done[0];
                    while (*p < 16u * (unsigned)t) { }
                }
            } else {
                unsigned needl = (layer == 1 ? 16u : 44u) * (unsigned)(t + 1);
                volatile unsigned* pl = &g_done[layer - 1];
                while (*pl < needl) { }
                if (t > 0) {
                    volatile unsigned* po = &g_done[layer];
                    while (*po < 44u * (unsigned)t) { }
                }
            }
            __threadfence();
        }
        __syncthreads();

        // ---- stage H (fp16) into smem [b][k] ----
        {
            const uint4 zz = make_uint4(0, 0, 0, 0);
            for (int e = tid; e < 32 * nch; e += NTHR) {
                int b = e >> chsh, c = e & (nch - 1);
                int k8 = c * 8;
                const ushort* sh = nullptr;
                if (layer == 0) {
                    if (t > 0)
                        sh = g_hh + (((size_t)(t - 1)) * 32 + b) * 512 + k8;
                } else {
                    if (k8 < 512)
                        sh = g_hh + (((size_t)(layer - 1) * Tsz + t) * 32 + b) * 512 + k8;
                    else if (t > 0)
                        sh = g_hh + (((size_t)layer * Tsz + (t - 1)) * 32 + b) * 512 + (k8 - 512);
                }
                uint4 vh = sh ? __ldcg((const uint4*)sh) : zz;
                *(uint4*)(Bh + b * rs + k8) = vh;
            }
        }
        __syncthreads();

        // ---- tensor-core GEMM: 1 m-tile x 2 nt x 32 ks per warp ----
        {
            float d[2][4] = {};
            bool active = !(t == 0 && (layer == 0 || kw == 1));
            if (active) {
                uint4 ah = __ldg(wp4);
                #pragma unroll
                for (int ks = 0; ks < 32; ks++) {
                    uint4 nx = ah;
                    if (ks < 31) nx = __ldg(wp4 + (ks + 1) * 32);
                    int k = kB + ks * 16;
                    #pragma unroll
                    for (int ntp = 0; ntp < 2; ntp++) {
                        int nt = np * 2 + ntp;
                        const ushort* ph = Bh + (nt * 8 + gr) * rs + k;
                        uint b0 = *(const uint*)ph, b1 = *(const uint*)(ph + 8);
                        mma_f16(d[ntp], ah, b0, b1);
                    }
                    ah = nx;
                }
            }
            float* pp = part + kw * PSTR;
            #pragma unroll
            for (int ntp = 0; ntp < 2; ntp++) {
                int sl0 = mw * 16 + gr;
                int bc = (np * 2 + ntp) * 8 + c0;
                pp[sl0 * 33 + bc]       = d[ntp][0];
                pp[sl0 * 33 + bc + 1]   = d[ntp][1];
                pp[(sl0 + 8) * 33 + bc]     = d[ntp][2];
                pp[(sl0 + 8) * 33 + bc + 1] = d[ntp][3];
            }
        }
        __syncthreads();

        // ---- merged reduce + activation + state update ----
        {
            size_t so = (((size_t)layer * Tsz + t)) * 32;
            float*  cout = g_c  + so * 512;
            ushort* hho  = g_hh + so * 512;
            const float* cprev = (t > 0) ? g_c + (((size_t)layer * Tsz + (t - 1)) * 32) * 512 : nullptr;
            if (layer == 0) {
                // single partial region (no K split)
                const float* xb = g_xt + ((size_t)t * 2048 + cta * 128) * 32;
                for (int it = tid; it < 1024; it += NTHR) {
                    int b = it >> 5, jj = it & 31;
                    int j = cta * 32 + jj;
                    float i_ = part[(0 * 32 + jj) * 33 + b] + __ldcg(xb + (0 * 32 + jj) * 32 + b);
                    float f_ = part[(1 * 32 + jj) * 33 + b] + __ldcg(xb + (1 * 32 + jj) * 32 + b);
                    float gg = part[(2 * 32 + jj) * 33 + b] + __ldcg(xb + (2 * 32 + jj) * 32 + b);
                    float o_ = part[(3 * 32 + jj) * 33 + b] + __ldcg(xb + (3 * 32 + jj) * 32 + b);
                    float cp = cprev ? __ldcg(cprev + (size_t)b * 512 + j) : 0.0f;
                    float cv = sigf(i_) * tanhef(gg) + sigf(f_) * cp;
                    float hv = sigf(o_) * tanhef(cv);
                    cout[(size_t)b * 512 + j] = cv;
                    hho[(size_t)b * 512 + j]  = f16of(hv);
                }
            } else {
                const float* clow = g_c + (((size_t)(layer - 1) * Tsz + t) * 32) * 512;
                const float* cb = ca_b + (size_t)(layer - 1) * G5;
                #define RED(SL, B) (part[(SL) * 33 + (B)] + part[PSTR + (SL) * 33 + (B)])
                for (int it = tid; it < nj * 32; it += NTHR) {
                    int b = it / nj, jj = it - b * nj;
                    int j = j0 + jj;
                    float i_ = RED(0 * nj + jj, b) + cb[0 * 512 + j];
                    float fp = RED(1 * nj + jj, b) + cb[1 * 512 + j];
                    float fl = RED(2 * nj + jj, b) + cb[2 * 512 + j];
                    float u_ = RED(3 * nj + jj, b) + cb[3 * 512 + j];
                    float o_ = RED(4 * nj + jj, b) + cb[4 * 512 + j];
                    float cp = cprev ? __ldcg(cprev + (size_t)b * 512 + j) : 0.0f;
                    float cl = __ldcg(clow + (size_t)b * 512 + j);
                    float cv = cp * sigf(fp + 1.0f) + cl * sigf(fl + 1.0f) + tanhef(u_) * sigf(i_);
                    float hv = sigf(o_) * tanhef(cv);
                    cout[(size_t)b * 512 + j] = cv;
                    hho[(size_t)b * 512 + j]  = f16of(hv);
                    if (layer == 3) {
                        out[(size_t)b * Tsz * Hsz + (size_t)t * Hsz + j] = hv;
                        out[BTHn + (size_t)b * Tsz * Hsz + (size_t)t * Hsz + j] = cv;
                        if (t == Tsz - 1) {
                            out[2 * BTHn + (size_t)b * Hsz + j] = hv;
                            out[2 * BTHn + (size_t)Bsz * Hsz + (size_t)b * Hsz + j] = cv;
                        }
                    }
                }
                #undef RED
            }
        }
        __syncthreads();

        // ---- publish completion of step t ----
        if (tid == 0) {
            __threadfence();
            atomicAdd(&g_done[layer], 1u);
        }
    }
}

extern "C" void kernel_launch(void* const* d_in, const int* in_sizes, int n_in,
                              void* d_out, int out_size)
{
    const float* x    = (const float*)d_in[0];
    const float* w_ih = (const float*)d_in[1];
    const float* w_hh = (const float*)d_in[2];
    const float* b_ih = (const float*)d_in[3];
    const float* b_hh = (const float*)d_in[4];
    const float* ca_w = (const float*)d_in[5];
    const float* ca_b = (const float*)d_in[6];
    float* out = (float*)d_out;
    (void)in_sizes; (void)n_in; (void)out_size;

    k_fill<<<296, 256>>>(w_hh, ca_w);

    dim3 g(G4 / 64, (Tsz * Bsz) / 64);
    k_xproj<<<g, 256>>>(x, w_ih, b_ih, b_hh);

    const int smem_bytes = PART_OFF + 2 * PSTR * 4;  // 66048 + 33792 = 99840
    cudaFuncSetAttribute(k_wave, cudaFuncAttributeMaxDynamicSharedMemorySize, smem_bytes);
    k_wave<<<NCTA, NTHR, smem_bytes>>>(ca_b, out);
}